// round 3
// baseline (speedup 1.0000x reference)
#include <cuda_runtime.h>

// ---------------------------------------------------------------------------
// Problem constants (shapes fixed by the dataset; N read at runtime anyway)
// ---------------------------------------------------------------------------
#define NMAX 50000

// Scratch (device globals; no allocation allowed)
__device__ float g_h  [NMAX * 256];   // GEMM output h of current layer
__device__ float g_buf[NMAX * 256];   // layer input / aggregation buffer
__device__ float g_als[NMAX * 4];
__device__ float g_ald[NMAX * 4];
__device__ float g_den[NMAX * 4];
__device__ float g_meff[64 * 64];
__device__ float g_beff[64];
__device__ int   g_idx64;             // 1 if edge_index is int64, 0 if int32

// ---------------------------------------------------------------------------
// Detect edge_index dtype. If data is int64 (values < N, high words zero),
// reading as int64 yields small non-negative values. If int32, each int64
// read combines two edges: value = lo + (hi<<32), astronomically large
// unless hi==0 (prob ~2e-5 per sample; 8 samples => negligible).
// ---------------------------------------------------------------------------
__global__ void detect_idx_kernel(const void* ei)
{
    const long long* p = (const long long*)ei;
    int ok64 = 1;
#pragma unroll
    for (int i = 0; i < 8; i++) {
        long long v = p[i];
        if (v < 0 || v >= NMAX) ok64 = 0;
    }
    g_idx64 = ok64;
}

__device__ __forceinline__ long long load_idx(const void* ei, long long i)
{
    if (g_idx64) return ((const long long*)ei)[i];
    return (long long)(((const int*)ei)[i]);
}

// ---------------------------------------------------------------------------
// SGEMM: C[N,M] = A[N,K] @ B[K,M], row-major, fp32.
// BM=128, BN=64, BK=16, 256 threads, 8x4 per thread.
// Requires: K % 16 == 0, M % 64 == 0. Row-guarded on N.
// ---------------------------------------------------------------------------
#define BM 128
#define BN 64
#define BKK 16
#define TM 8
#define TN 4

__global__ __launch_bounds__(256) void sgemm_kernel(
    const float* __restrict__ A, const float* __restrict__ B,
    float* __restrict__ C, int Nrows, int K, int M)
{
    __shared__ float As[BKK][BM];
    __shared__ float Bs[BKK][BN];

    const int tid = threadIdx.x;
    const int block_row = blockIdx.y * BM;
    const int block_col = blockIdx.x * BN;

    const int aRow  = tid >> 2;        // 0..63, two iterations cover 128 rows
    const int aCol4 = tid & 3;         // float4 column within BK=16
    const int bRow  = tid >> 4;        // 0..15
    const int bCol4 = tid & 15;        // float4 within BN=64

    const int ty = tid >> 4;           // 0..15 -> row group
    const int tx = tid & 15;           // 0..15 -> col group

    float acc[TM][TN];
#pragma unroll
    for (int i = 0; i < TM; i++)
#pragma unroll
        for (int j = 0; j < TN; j++) acc[i][j] = 0.f;

    for (int k0 = 0; k0 < K; k0 += BKK) {
        // load A tile (transposed into As[k][row])
#pragma unroll
        for (int it = 0; it < 2; it++) {
            int r    = aRow + it * 64;
            int grow = block_row + r;
            float4 v = make_float4(0.f, 0.f, 0.f, 0.f);
            if (grow < Nrows)
                v = *(const float4*)&A[(size_t)grow * K + k0 + aCol4 * 4];
            As[aCol4 * 4 + 0][r] = v.x;
            As[aCol4 * 4 + 1][r] = v.y;
            As[aCol4 * 4 + 2][r] = v.z;
            As[aCol4 * 4 + 3][r] = v.w;
        }
        // load B tile
        {
            float4 v = *(const float4*)&B[(size_t)(k0 + bRow) * M + block_col + bCol4 * 4];
            *(float4*)&Bs[bRow][bCol4 * 4] = v;
        }
        __syncthreads();

#pragma unroll
        for (int k = 0; k < BKK; k++) {
            float ra[TM], rb[TN];
            float4 a0 = *(const float4*)&As[k][ty * TM];
            float4 a1 = *(const float4*)&As[k][ty * TM + 4];
            ra[0]=a0.x; ra[1]=a0.y; ra[2]=a0.z; ra[3]=a0.w;
            ra[4]=a1.x; ra[5]=a1.y; ra[6]=a1.z; ra[7]=a1.w;
            float4 b0 = *(const float4*)&Bs[k][tx * TN];
            rb[0]=b0.x; rb[1]=b0.y; rb[2]=b0.z; rb[3]=b0.w;
#pragma unroll
            for (int i = 0; i < TM; i++)
#pragma unroll
                for (int j = 0; j < TN; j++)
                    acc[i][j] = fmaf(ra[i], rb[j], acc[i][j]);
        }
        __syncthreads();
    }

#pragma unroll
    for (int i = 0; i < TM; i++) {
        int grow = block_row + ty * TM + i;
        if (grow < Nrows) {
            float4 v = make_float4(acc[i][0], acc[i][1], acc[i][2], acc[i][3]);
            *(float4*)&C[(size_t)grow * M + block_col + tx * TN] = v;
        }
    }
}

// ---------------------------------------------------------------------------
// Per-node attention logits: al_s[n,h] = <h[n,h,:], a_src[h,:]>, same for dst.
// One warp per node, loops heads.
// ---------------------------------------------------------------------------
template <int H>
__global__ void compute_al_kernel(const float* __restrict__ h,
                                  const float* __restrict__ a_src,
                                  const float* __restrict__ a_dst,
                                  float* __restrict__ als,
                                  float* __restrict__ ald, int N)
{
    int n    = (blockIdx.x * blockDim.x + threadIdx.x) >> 5;
    int lane = threadIdx.x & 31;
    if (n >= N) return;
    const float* hn = h + (size_t)n * (H * 64);
#pragma unroll
    for (int hd = 0; hd < H; hd++) {
        float v1 = hn[hd * 64 + lane];
        float v2 = hn[hd * 64 + 32 + lane];
        float s  = v1 * a_src[hd * 64 + lane] + v2 * a_src[hd * 64 + 32 + lane];
        float d  = v1 * a_dst[hd * 64 + lane] + v2 * a_dst[hd * 64 + 32 + lane];
#pragma unroll
        for (int o = 16; o > 0; o >>= 1) {
            s += __shfl_down_sync(0xffffffffu, s, o);
            d += __shfl_down_sync(0xffffffffu, d, o);
        }
        if (lane == 0) {
            als[n * H + hd] = s;
            ald[n * H + hd] = d;
        }
    }
}

// ---------------------------------------------------------------------------
// Single-pass edge scatter: agg[dst] += exp(lrelu(al_s[src]+al_d[dst])) * h[src]
//                           den[dst] += exp(...)
// Uses red.global.add.v4.f32 for the message accumulation.
// ---------------------------------------------------------------------------
template <int H>
__global__ __launch_bounds__(256) void edge_scatter_kernel(
    const void* __restrict__ ei, int E,
    const float* __restrict__ hsrc,
    const float* __restrict__ als, const float* __restrict__ ald,
    float* __restrict__ agg, float* __restrict__ den)
{
    constexpr int F4  = H * 16;                 // float4 per edge
    constexpr int LPE = (F4 < 32) ? F4 : 32;    // lanes per edge
    constexpr int EPW = 32 / LPE;               // edges per warp
    constexpr int F4L = (F4 + 31) / 32;         // float4 per lane

    int gwarp = (blockIdx.x * blockDim.x + threadIdx.x) >> 5;
    int lane  = threadIdx.x & 31;
    int sub   = lane % LPE;
    int e     = gwarp * EPW + lane / LPE;
    bool valid = (e < E);

    long long src = 0, dst = 0;
    if (valid) {
        src = load_idx(ei, e);
        dst = load_idx(ei, (long long)E + e);
    }

    float exv = 0.f;
    if (valid && sub < H) {
        float s  = als[src * H + sub] + ald[dst * H + sub];
        float lr = s > 0.f ? s : 0.2f * s;
        exv = __expf(lr);
        atomicAdd(&den[dst * H + sub], exv);
    }
    int base = lane - sub;

#pragma unroll
    for (int t = 0; t < F4L; t++) {
        int   q    = sub + t * 32;
        int   head = q >> 4;
        float ex   = __shfl_sync(0xffffffffu, exv, base + head);
        if (valid) {
            const float4 hv = *(const float4*)(hsrc + src * (size_t)(F4 * 4) + q * 4);
            float4 v = make_float4(hv.x * ex, hv.y * ex, hv.z * ex, hv.w * ex);
            float* p = agg + dst * (size_t)(F4 * 4) + q * 4;
            asm volatile("red.global.add.v4.f32 [%0], {%1,%2,%3,%4};"
                         :: "l"(p), "f"(v.x), "f"(v.y), "f"(v.z), "f"(v.w)
                         : "memory");
        }
    }
}

// ---------------------------------------------------------------------------
// Normalize + self-loop + bias (+ optional ELU). In-place on agg.
// ---------------------------------------------------------------------------
template <int H, bool DOELU>
__global__ void finalize_kernel(const float* __restrict__ hbuf,
                                float* __restrict__ agg,
                                const float* __restrict__ als,
                                const float* __restrict__ ald,
                                const float* __restrict__ den,
                                const float* __restrict__ bias, int N)
{
    constexpr int F4 = H * 16;
    int idx = blockIdx.x * blockDim.x + threadIdx.x;     // over N*F4 float4s
    if (idx >= N * F4) return;
    int n = idx / F4, q = idx - n * F4;
    int hd = q >> 4;

    float s   = als[n * H + hd] + ald[n * H + hd];
    float lr  = s > 0.f ? s : 0.2f * s;
    float exs = __expf(lr);
    float inv = 1.f / (den[n * H + hd] + exs + 1e-16f);

    float4 hv = *(const float4*)(hbuf + (size_t)idx * 4);
    float4 av = *(const float4*)(agg + (size_t)idx * 4);
    float4 bv = *(const float4*)(bias + q * 4);
    float4 o;
    o.x = (av.x + exs * hv.x) * inv + bv.x;
    o.y = (av.y + exs * hv.y) * inv + bv.y;
    o.z = (av.z + exs * hv.z) * inv + bv.z;
    o.w = (av.w + exs * hv.w) * inv + bv.w;
    if (DOELU) {
        o.x = o.x > 0.f ? o.x : (__expf(o.x) - 1.f);
        o.y = o.y > 0.f ? o.y : (__expf(o.y) - 1.f);
        o.z = o.z > 0.f ? o.z : (__expf(o.z) - 1.f);
        o.w = o.w > 0.f ? o.w : (__expf(o.w) - 1.f);
    }
    *(float4*)(agg + (size_t)idx * 4) = o;
}

// ---------------------------------------------------------------------------
// Fold MHA (seq_len=1 => softmax == 1 => a = h @ (Wo @ Wqkv_v)^T + (Wo bqkv_v + bo))
// ---------------------------------------------------------------------------
__global__ void prep_meff_kernel(const float* __restrict__ Wqkv,
                                 const float* __restrict__ bqkv,
                                 const float* __restrict__ Wo,
                                 const float* __restrict__ bo,
                                 float* __restrict__ Meff,
                                 float* __restrict__ beff)
{
    int idx = threadIdx.x;
    for (int t = idx; t < 4096; t += blockDim.x) {
        int i = t >> 6, j = t & 63;
        float s = 0.f;
#pragma unroll
        for (int k = 0; k < 64; k++)
            s += Wo[i * 64 + k] * Wqkv[(128 + k) * 64 + j];
        Meff[t] = s;
    }
    if (idx < 64) {
        float s = bo[idx];
#pragma unroll
        for (int k = 0; k < 64; k++)
            s += Wo[idx * 64 + k] * bqkv[128 + k];
        beff[idx] = s;
    }
}

// ---------------------------------------------------------------------------
// Final: a = h3 @ Meff^T + beff, then three linear heads (+ sigmoid on 2).
// Output layout: [N*3 logits][N cpu][N mem]
// ---------------------------------------------------------------------------
__global__ __launch_bounds__(128) void heads_kernel(
    const float* __restrict__ h3,
    const float* __restrict__ Meff, const float* __restrict__ beff,
    const float* __restrict__ Wlin, const float* __restrict__ blin,
    const float* __restrict__ Wcpu, const float* __restrict__ bcpu,
    const float* __restrict__ Wmem, const float* __restrict__ bmem,
    float* __restrict__ out, int N)
{
    __shared__ float sM[64 * 64];
    __shared__ float sbeff[64];
    __shared__ float sW[5 * 64];
    __shared__ float sbb[5];

    int tid = threadIdx.x;
    for (int t = tid; t < 4096; t += blockDim.x) sM[t] = Meff[t];
    if (tid < 64) sbeff[tid] = beff[tid];
    for (int t = tid; t < 192; t += blockDim.x) sW[t] = Wlin[t];
    if (tid < 64) sW[192 + tid] = Wcpu[tid];
    if (tid < 64) sW[256 + tid] = Wmem[tid];
    if (tid == 0) { sbb[0]=blin[0]; sbb[1]=blin[1]; sbb[2]=blin[2]; sbb[3]=bcpu[0]; sbb[4]=bmem[0]; }
    __syncthreads();

    int n = blockIdx.x * blockDim.x + tid;
    if (n >= N) return;

    float hreg[64];
    const float4* hp = (const float4*)(h3 + (size_t)n * 64);
#pragma unroll
    for (int i = 0; i < 16; i++) {
        float4 v = hp[i];
        hreg[i*4+0]=v.x; hreg[i*4+1]=v.y; hreg[i*4+2]=v.z; hreg[i*4+3]=v.w;
    }

    float o0 = sbb[0], o1 = sbb[1], o2 = sbb[2], o3 = sbb[3], o4 = sbb[4];
    for (int i = 0; i < 64; i++) {
        float a = sbeff[i];
        const float* mi = &sM[i * 64];
#pragma unroll
        for (int j = 0; j < 64; j++) a = fmaf(hreg[j], mi[j], a);
        o0 = fmaf(sW[0 * 64 + i], a, o0);
        o1 = fmaf(sW[1 * 64 + i], a, o1);
        o2 = fmaf(sW[2 * 64 + i], a, o2);
        o3 = fmaf(sW[3 * 64 + i], a, o3);
        o4 = fmaf(sW[4 * 64 + i], a, o4);
    }
    out[n * 3 + 0] = o0;
    out[n * 3 + 1] = o1;
    out[n * 3 + 2] = o2;
    out[3 * N + n] = 1.f / (1.f + __expf(-o3));
    out[4 * N + n] = 1.f / (1.f + __expf(-o4));
}

// ---------------------------------------------------------------------------
// Host-side orchestration
// ---------------------------------------------------------------------------
static inline void run_gemm(const float* A, const float* B, float* C,
                            int Nrows, int K, int M)
{
    dim3 grid(M / BN, (Nrows + BM - 1) / BM);
    sgemm_kernel<<<grid, 256>>>(A, B, C, Nrows, K, M);
}

extern "C" void kernel_launch(void* const* d_in, const int* in_sizes, int n_in,
                              void* d_out, int out_size)
{
    const float* x    = (const float*)d_in[0];
    const void*  ei   = d_in[1];               // int32 or int64, detected on device
    const float* W1   = (const float*)d_in[2];
    const float* as1  = (const float*)d_in[3];
    const float* ad1  = (const float*)d_in[4];
    const float* b1   = (const float*)d_in[5];
    const float* W2   = (const float*)d_in[6];
    const float* as2  = (const float*)d_in[7];
    const float* ad2  = (const float*)d_in[8];
    const float* b2   = (const float*)d_in[9];
    const float* W3   = (const float*)d_in[10];
    const float* as3  = (const float*)d_in[11];
    const float* ad3  = (const float*)d_in[12];
    const float* b3   = (const float*)d_in[13];
    const float* Wqkv = (const float*)d_in[14];
    const float* bqkv = (const float*)d_in[15];
    const float* Wo   = (const float*)d_in[16];
    const float* bo   = (const float*)d_in[17];
    const float* Wlin = (const float*)d_in[18];
    const float* blin = (const float*)d_in[19];
    const float* Wcpu = (const float*)d_in[20];
    const float* bcpu = (const float*)d_in[21];
    const float* Wmem = (const float*)d_in[22];
    const float* bmem = (const float*)d_in[23];

    const int N = in_sizes[0] / 256;
    const int E = in_sizes[1] / 2;

    float *h, *buf, *als, *ald, *den, *meff, *beff;
    cudaGetSymbolAddress((void**)&h,    g_h);
    cudaGetSymbolAddress((void**)&buf,  g_buf);
    cudaGetSymbolAddress((void**)&als,  g_als);
    cudaGetSymbolAddress((void**)&ald,  g_ald);
    cudaGetSymbolAddress((void**)&den,  g_den);
    cudaGetSymbolAddress((void**)&meff, g_meff);
    cudaGetSymbolAddress((void**)&beff, g_beff);

    const int al_blocks = (N * 32 + 255) / 256;

    detect_idx_kernel<<<1, 1>>>(ei);

    // ---------------- Layer 1: H=4 (Fin=256 -> 256) ----------------
    run_gemm(x, W1, h, N, 256, 256);
    compute_al_kernel<4><<<al_blocks, 256>>>(h, as1, ad1, als, ald, N);
    cudaMemsetAsync(buf, 0, (size_t)N * 256 * sizeof(float));
    cudaMemsetAsync(den, 0, (size_t)N * 4 * sizeof(float));
    {
        int warps  = E;                       // EPW=1 for H=4
        int blocks = (warps * 32 + 255) / 256;
        edge_scatter_kernel<4><<<blocks, 256>>>(ei, E, h, als, ald, buf, den);
    }
    finalize_kernel<4, true><<<(N * 64 + 255) / 256, 256>>>(h, buf, als, ald, den, b1, N);

    // ---------------- Layer 2: H=2 (256 -> 128) ----------------
    run_gemm(buf, W2, h, N, 256, 128);
    compute_al_kernel<2><<<al_blocks, 256>>>(h, as2, ad2, als, ald, N);
    cudaMemsetAsync(buf, 0, (size_t)N * 128 * sizeof(float));
    cudaMemsetAsync(den, 0, (size_t)N * 2 * sizeof(float));
    {
        int warps  = E;                       // EPW=1 for H=2
        int blocks = (warps * 32 + 255) / 256;
        edge_scatter_kernel<2><<<blocks, 256>>>(ei, E, h, als, ald, buf, den);
    }
    finalize_kernel<2, true><<<(N * 32 + 255) / 256, 256>>>(h, buf, als, ald, den, b2, N);

    // ---------------- Layer 3: H=1 (128 -> 64) ----------------
    run_gemm(buf, W3, h, N, 128, 64);
    compute_al_kernel<1><<<al_blocks, 256>>>(h, as3, ad3, als, ald, N);
    cudaMemsetAsync(buf, 0, (size_t)N * 64 * sizeof(float));
    cudaMemsetAsync(den, 0, (size_t)N * 1 * sizeof(float));
    {
        int warps  = (E + 1) / 2;             // EPW=2 for H=1
        int blocks = (warps * 32 + 255) / 256;
        edge_scatter_kernel<1><<<blocks, 256>>>(ei, E, h, als, ald, buf, den);
    }
    finalize_kernel<1, false><<<(N * 16 + 255) / 256, 256>>>(h, buf, als, ald, den, b3, N);

    // ---------------- MHA (identity softmax) + heads ----------------
    prep_meff_kernel<<<1, 256>>>(Wqkv, bqkv, Wo, bo, meff, beff);
    heads_kernel<<<(N + 127) / 128, 128>>>(buf, meff, beff,
                                           Wlin, blin, Wcpu, bcpu, Wmem, bmem,
                                           (float*)d_out, N);
}

// round 4
// speedup vs baseline: 1.0679x; 1.0679x over previous
#include <cuda_runtime.h>

// ---------------------------------------------------------------------------
// Problem constants (shapes fixed by the dataset; N/E read at runtime)
// ---------------------------------------------------------------------------
#define NMAX 50000
#define EMAX 1000000

// Scratch (device globals; no allocation allowed)
__device__ float g_h  [NMAX * 256];   // GEMM output h of current layer
__device__ float g_buf[NMAX * 256];   // layer input / output buffer
__device__ float g_als[NMAX * 4];
__device__ float g_ald[NMAX * 4];
__device__ float g_meff[64 * 64];
__device__ float g_beff[64];
__device__ int   g_idx64;             // 1 if edge_index is int64, 0 if int32
__device__ int   g_cnt   [NMAX];
__device__ int   g_woff  [NMAX];
__device__ int   g_rowptr[NMAX + 1];
__device__ int   g_csr   [EMAX];

// ---------------------------------------------------------------------------
// Edge index dtype detection (int64 vs int32 stored in the same buffer).
// ---------------------------------------------------------------------------
__global__ void detect_idx_kernel(const void* ei)
{
    const long long* p = (const long long*)ei;
    int ok64 = 1;
#pragma unroll
    for (int i = 0; i < 8; i++) {
        long long v = p[i];
        if (v < 0 || v >= NMAX) ok64 = 0;
    }
    g_idx64 = ok64;
}

__device__ __forceinline__ int load_idx(const void* ei, long long i)
{
    if (g_idx64) return (int)((const long long*)ei)[i];
    return ((const int*)ei)[i];
}

// ---------------------------------------------------------------------------
// CSR build (graph is reused by all 3 layers)
// ---------------------------------------------------------------------------
__global__ void count_kernel(const void* __restrict__ ei, int E, int* __restrict__ cnt)
{
    int e = blockIdx.x * blockDim.x + threadIdx.x;
    if (e < E) {
        int d = load_idx(ei, (long long)E + e);
        atomicAdd(&cnt[d], 1);
    }
}

// Single-block exclusive scan over N counts -> rowptr (+ copy to woff).
__global__ __launch_bounds__(1024) void scan_kernel(
    const int* __restrict__ cnt, int* __restrict__ rowptr,
    int* __restrict__ woff, int N)
{
    __shared__ int ssum[1024];
    int t = threadIdx.x;
    int chunk = (N + 1023) / 1024;
    int s0 = t * chunk, s1 = min(s0 + chunk, N);
    if (s0 > N) s0 = N;

    int sum = 0;
    for (int i = s0; i < s1; i++) sum += cnt[i];
    ssum[t] = sum;
    __syncthreads();
    // Hillis-Steele inclusive scan
    for (int o = 1; o < 1024; o <<= 1) {
        int v = (t >= o) ? ssum[t - o] : 0;
        __syncthreads();
        ssum[t] += v;
        __syncthreads();
    }
    int run = (t == 0) ? 0 : ssum[t - 1];
    for (int i = s0; i < s1; i++) {
        rowptr[i] = run;
        woff[i]   = run;
        run += cnt[i];
    }
    if (t == 1023) rowptr[N] = ssum[1023];
}

__global__ void fill_kernel(const void* __restrict__ ei, int E,
                            int* __restrict__ woff, int* __restrict__ csr_src)
{
    int e = blockIdx.x * blockDim.x + threadIdx.x;
    if (e < E) {
        int s = load_idx(ei, e);
        int d = load_idx(ei, (long long)E + e);
        int pos = atomicAdd(&woff[d], 1);
        csr_src[pos] = s;
    }
}

// ---------------------------------------------------------------------------
// SGEMM: C[N,M] = A[N,K] @ B[K,M], row-major, fp32.
// BM=128, BN=64, BK=16, 256 threads, 8x4 per thread.
// ---------------------------------------------------------------------------
#define BM 128
#define BN 64
#define BKK 16
#define TM 8
#define TN 4

__global__ __launch_bounds__(256) void sgemm_kernel(
    const float* __restrict__ A, const float* __restrict__ B,
    float* __restrict__ C, int Nrows, int K, int M)
{
    __shared__ float As[BKK][BM];
    __shared__ float Bs[BKK][BN];

    const int tid = threadIdx.x;
    const int block_row = blockIdx.y * BM;
    const int block_col = blockIdx.x * BN;

    const int aRow  = tid >> 2;
    const int aCol4 = tid & 3;
    const int bRow  = tid >> 4;
    const int bCol4 = tid & 15;

    const int ty = tid >> 4;
    const int tx = tid & 15;

    float acc[TM][TN];
#pragma unroll
    for (int i = 0; i < TM; i++)
#pragma unroll
        for (int j = 0; j < TN; j++) acc[i][j] = 0.f;

    for (int k0 = 0; k0 < K; k0 += BKK) {
#pragma unroll
        for (int it = 0; it < 2; it++) {
            int r    = aRow + it * 64;
            int grow = block_row + r;
            float4 v = make_float4(0.f, 0.f, 0.f, 0.f);
            if (grow < Nrows)
                v = *(const float4*)&A[(size_t)grow * K + k0 + aCol4 * 4];
            As[aCol4 * 4 + 0][r] = v.x;
            As[aCol4 * 4 + 1][r] = v.y;
            As[aCol4 * 4 + 2][r] = v.z;
            As[aCol4 * 4 + 3][r] = v.w;
        }
        {
            float4 v = *(const float4*)&B[(size_t)(k0 + bRow) * M + block_col + bCol4 * 4];
            *(float4*)&Bs[bRow][bCol4 * 4] = v;
        }
        __syncthreads();

#pragma unroll
        for (int k = 0; k < BKK; k++) {
            float ra[TM], rb[TN];
            float4 a0 = *(const float4*)&As[k][ty * TM];
            float4 a1 = *(const float4*)&As[k][ty * TM + 4];
            ra[0]=a0.x; ra[1]=a0.y; ra[2]=a0.z; ra[3]=a0.w;
            ra[4]=a1.x; ra[5]=a1.y; ra[6]=a1.z; ra[7]=a1.w;
            float4 b0 = *(const float4*)&Bs[k][tx * TN];
            rb[0]=b0.x; rb[1]=b0.y; rb[2]=b0.z; rb[3]=b0.w;
#pragma unroll
            for (int i = 0; i < TM; i++)
#pragma unroll
                for (int j = 0; j < TN; j++)
                    acc[i][j] = fmaf(ra[i], rb[j], acc[i][j]);
        }
        __syncthreads();
    }

#pragma unroll
    for (int i = 0; i < TM; i++) {
        int grow = block_row + ty * TM + i;
        if (grow < Nrows) {
            float4 v = make_float4(acc[i][0], acc[i][1], acc[i][2], acc[i][3]);
            *(float4*)&C[(size_t)grow * M + block_col + tx * TN] = v;
        }
    }
}

// ---------------------------------------------------------------------------
// Per-node attention logits
// ---------------------------------------------------------------------------
template <int H>
__global__ void compute_al_kernel(const float* __restrict__ h,
                                  const float* __restrict__ a_src,
                                  const float* __restrict__ a_dst,
                                  float* __restrict__ als,
                                  float* __restrict__ ald, int N)
{
    int n    = (blockIdx.x * blockDim.x + threadIdx.x) >> 5;
    int lane = threadIdx.x & 31;
    if (n >= N) return;
    const float* hn = h + (size_t)n * (H * 64);
#pragma unroll
    for (int hd = 0; hd < H; hd++) {
        float v1 = hn[hd * 64 + lane];
        float v2 = hn[hd * 64 + 32 + lane];
        float s  = v1 * a_src[hd * 64 + lane] + v2 * a_src[hd * 64 + 32 + lane];
        float d  = v1 * a_dst[hd * 64 + lane] + v2 * a_dst[hd * 64 + 32 + lane];
#pragma unroll
        for (int o = 16; o > 0; o >>= 1) {
            s += __shfl_down_sync(0xffffffffu, s, o);
            d += __shfl_down_sync(0xffffffffu, d, o);
        }
        if (lane == 0) {
            als[n * H + hd] = s;
            ald[n * H + hd] = d;
        }
    }
}

// ---------------------------------------------------------------------------
// Fused CSR gather: for each dst node, accumulate softmax-weighted neighbor
// messages + self loop, normalize, add bias, optional ELU. One pass, no
// atomics, each output written exactly once.
// ---------------------------------------------------------------------------
template <int H, bool DOELU>
__global__ __launch_bounds__(256) void gat_gather_kernel(
    const int* __restrict__ rowptr, const int* __restrict__ csr_src,
    const float* __restrict__ h, const float* __restrict__ als,
    const float* __restrict__ ald, const float* __restrict__ bias,
    float* __restrict__ out, int N)
{
    constexpr int F4  = H * 16;                 // float4 per node row
    constexpr int LPE = (F4 < 32) ? F4 : 32;    // lanes per node
    constexpr int NPW = 32 / LPE;               // nodes per warp
    constexpr int F4L = (F4 + 31) / 32;         // float4 per lane

    int gwarp = (blockIdx.x * blockDim.x + threadIdx.x) >> 5;
    int lane  = threadIdx.x & 31;
    int sub   = lane % LPE;
    int base  = lane - sub;
    int n     = gwarp * NPW + lane / LPE;
    bool valid = (n < N);
    if (!valid) n = 0;                          // keep all lanes for shuffles

    int rb = rowptr[n], re = rowptr[n + 1];

    float aldh = 0.f, alsh = 0.f;
    if (sub < H) {
        aldh = ald[(size_t)n * H + sub];
        alsh = als[(size_t)n * H + sub];
    }

    float4 acc[F4L];
#pragma unroll
    for (int t = 0; t < F4L; t++) acc[t] = make_float4(0.f, 0.f, 0.f, 0.f);
    float den = 0.f;

    // self loop
    {
        float exs = 0.f;
        if (sub < H) {
            float s = alsh + aldh;
            s = s > 0.f ? s : 0.2f * s;
            exs = __expf(s);
            den = exs;
        }
#pragma unroll
        for (int t = 0; t < F4L; t++) {
            int q = sub + t * LPE;
            float ex = __shfl_sync(0xffffffffu, exs, base + (q >> 4));
            float4 hv = *(const float4*)(h + (size_t)n * (F4 * 4) + q * 4);
            acc[t].x += hv.x * ex; acc[t].y += hv.y * ex;
            acc[t].z += hv.z * ex; acc[t].w += hv.w * ex;
        }
    }

    // neighbors, prefetching next edge's src + als
    int   src_cur = 0; float al_cur = 0.f;
    if (rb < re) {
        src_cur = csr_src[rb];
        if (sub < H) al_cur = als[(size_t)src_cur * H + sub];
    }
    for (int e = rb; e < re; e++) {
        int   srcc = src_cur;
        float alv  = al_cur;
        if (e + 1 < re) {
            src_cur = csr_src[e + 1];
            if (sub < H) al_cur = als[(size_t)src_cur * H + sub];
        }
        float exv = 0.f;
        if (sub < H) {
            float s = alv + aldh;
            s = s > 0.f ? s : 0.2f * s;
            exv = __expf(s);
            den += exv;
        }
#pragma unroll
        for (int t = 0; t < F4L; t++) {
            int q = sub + t * LPE;
            float ex = __shfl_sync(0xffffffffu, exv, base + (q >> 4));
            float4 hv = *(const float4*)(h + (size_t)srcc * (F4 * 4) + q * 4);
            acc[t].x += hv.x * ex; acc[t].y += hv.y * ex;
            acc[t].z += hv.z * ex; acc[t].w += hv.w * ex;
        }
    }

    // normalize + bias (+ ELU) + store
    float inv = 0.f;
    if (sub < H) inv = 1.f / (den + 1e-16f);
#pragma unroll
    for (int t = 0; t < F4L; t++) {
        int q = sub + t * LPE;
        float iv = __shfl_sync(0xffffffffu, inv, base + (q >> 4));
        float4 bv = *(const float4*)(bias + q * 4);
        float4 o;
        o.x = acc[t].x * iv + bv.x;
        o.y = acc[t].y * iv + bv.y;
        o.z = acc[t].z * iv + bv.z;
        o.w = acc[t].w * iv + bv.w;
        if (DOELU) {
            o.x = o.x > 0.f ? o.x : (__expf(o.x) - 1.f);
            o.y = o.y > 0.f ? o.y : (__expf(o.y) - 1.f);
            o.z = o.z > 0.f ? o.z : (__expf(o.z) - 1.f);
            o.w = o.w > 0.f ? o.w : (__expf(o.w) - 1.f);
        }
        if (valid)
            *(float4*)(out + (size_t)n * (F4 * 4) + q * 4) = o;
    }
}

// ---------------------------------------------------------------------------
// Fold MHA (seq_len=1 => softmax == 1 => a = h @ (Wo @ Wqkv_v)^T + fold bias)
// ---------------------------------------------------------------------------
__global__ void prep_meff_kernel(const float* __restrict__ Wqkv,
                                 const float* __restrict__ bqkv,
                                 const float* __restrict__ Wo,
                                 const float* __restrict__ bo,
                                 float* __restrict__ Meff,
                                 float* __restrict__ beff)
{
    int idx = threadIdx.x;
    for (int t = idx; t < 4096; t += blockDim.x) {
        int i = t >> 6, j = t & 63;
        float s = 0.f;
#pragma unroll
        for (int k = 0; k < 64; k++)
            s += Wo[i * 64 + k] * Wqkv[(128 + k) * 64 + j];
        Meff[t] = s;
    }
    if (idx < 64) {
        float s = bo[idx];
#pragma unroll
        for (int k = 0; k < 64; k++)
            s += Wo[idx * 64 + k] * bqkv[128 + k];
        beff[idx] = s;
    }
}

// ---------------------------------------------------------------------------
// Final heads
// ---------------------------------------------------------------------------
__global__ __launch_bounds__(128) void heads_kernel(
    const float* __restrict__ h3,
    const float* __restrict__ Meff, const float* __restrict__ beff,
    const float* __restrict__ Wlin, const float* __restrict__ blin,
    const float* __restrict__ Wcpu, const float* __restrict__ bcpu,
    const float* __restrict__ Wmem, const float* __restrict__ bmem,
    float* __restrict__ out, int N)
{
    __shared__ float sM[64 * 64];
    __shared__ float sbeff[64];
    __shared__ float sW[5 * 64];
    __shared__ float sbb[5];

    int tid = threadIdx.x;
    for (int t = tid; t < 4096; t += blockDim.x) sM[t] = Meff[t];
    if (tid < 64) sbeff[tid] = beff[tid];
    for (int t = tid; t < 192; t += blockDim.x) sW[t] = Wlin[t];
    if (tid < 64) sW[192 + tid] = Wcpu[tid];
    if (tid < 64) sW[256 + tid] = Wmem[tid];
    if (tid == 0) { sbb[0]=blin[0]; sbb[1]=blin[1]; sbb[2]=blin[2]; sbb[3]=bcpu[0]; sbb[4]=bmem[0]; }
    __syncthreads();

    int n = blockIdx.x * blockDim.x + tid;
    if (n >= N) return;

    float hreg[64];
    const float4* hp = (const float4*)(h3 + (size_t)n * 64);
#pragma unroll
    for (int i = 0; i < 16; i++) {
        float4 v = hp[i];
        hreg[i*4+0]=v.x; hreg[i*4+1]=v.y; hreg[i*4+2]=v.z; hreg[i*4+3]=v.w;
    }

    float o0 = sbb[0], o1 = sbb[1], o2 = sbb[2], o3 = sbb[3], o4 = sbb[4];
    for (int i = 0; i < 64; i++) {
        float a = sbeff[i];
        const float* mi = &sM[i * 64];
#pragma unroll
        for (int j = 0; j < 64; j++) a = fmaf(hreg[j], mi[j], a);
        o0 = fmaf(sW[0 * 64 + i], a, o0);
        o1 = fmaf(sW[1 * 64 + i], a, o1);
        o2 = fmaf(sW[2 * 64 + i], a, o2);
        o3 = fmaf(sW[3 * 64 + i], a, o3);
        o4 = fmaf(sW[4 * 64 + i], a, o4);
    }
    out[n * 3 + 0] = o0;
    out[n * 3 + 1] = o1;
    out[n * 3 + 2] = o2;
    out[3 * N + n] = 1.f / (1.f + __expf(-o3));
    out[4 * N + n] = 1.f / (1.f + __expf(-o4));
}

// ---------------------------------------------------------------------------
// Host-side orchestration
// ---------------------------------------------------------------------------
static inline void run_gemm(const float* A, const float* B, float* C,
                            int Nrows, int K, int M)
{
    dim3 grid(M / BN, (Nrows + BM - 1) / BM);
    sgemm_kernel<<<grid, 256>>>(A, B, C, Nrows, K, M);
}

template <int H, bool DOELU>
static inline void run_gather(const int* rowptr, const int* csr,
                              const float* h, const float* als,
                              const float* ald, const float* bias,
                              float* out, int N)
{
    constexpr int F4  = H * 16;
    constexpr int LPE = (F4 < 32) ? F4 : 32;
    constexpr int NPW = 32 / LPE;
    int warps  = (N + NPW - 1) / NPW;
    int blocks = (warps * 32 + 255) / 256;
    gat_gather_kernel<H, DOELU><<<blocks, 256>>>(rowptr, csr, h, als, ald, bias, out, N);
}

extern "C" void kernel_launch(void* const* d_in, const int* in_sizes, int n_in,
                              void* d_out, int out_size)
{
    const float* x    = (const float*)d_in[0];
    const void*  ei   = d_in[1];               // int32 or int64, detected on device
    const float* W1   = (const float*)d_in[2];
    const float* as1  = (const float*)d_in[3];
    const float* ad1  = (const float*)d_in[4];
    const float* b1   = (const float*)d_in[5];
    const float* W2   = (const float*)d_in[6];
    const float* as2  = (const float*)d_in[7];
    const float* ad2  = (const float*)d_in[8];
    const float* b2   = (const float*)d_in[9];
    const float* W3   = (const float*)d_in[10];
    const float* as3  = (const float*)d_in[11];
    const float* ad3  = (const float*)d_in[12];
    const float* b3   = (const float*)d_in[13];
    const float* Wqkv = (const float*)d_in[14];
    const float* bqkv = (const float*)d_in[15];
    const float* Wo   = (const float*)d_in[16];
    const float* bo   = (const float*)d_in[17];
    const float* Wlin = (const float*)d_in[18];
    const float* blin = (const float*)d_in[19];
    const float* Wcpu = (const float*)d_in[20];
    const float* bcpu = (const float*)d_in[21];
    const float* Wmem = (const float*)d_in[22];
    const float* bmem = (const float*)d_in[23];

    const int N = in_sizes[0] / 256;
    const int E = in_sizes[1] / 2;

    float *h, *buf, *als, *ald, *meff, *beff;
    int *cnt, *woff, *rowptr, *csr;
    cudaGetSymbolAddress((void**)&h,      g_h);
    cudaGetSymbolAddress((void**)&buf,    g_buf);
    cudaGetSymbolAddress((void**)&als,    g_als);
    cudaGetSymbolAddress((void**)&ald,    g_ald);
    cudaGetSymbolAddress((void**)&meff,   g_meff);
    cudaGetSymbolAddress((void**)&beff,   g_beff);
    cudaGetSymbolAddress((void**)&cnt,    g_cnt);
    cudaGetSymbolAddress((void**)&woff,   g_woff);
    cudaGetSymbolAddress((void**)&rowptr, g_rowptr);
    cudaGetSymbolAddress((void**)&csr,    g_csr);

    const int al_blocks = (N * 32 + 255) / 256;
    const int e_blocks  = (E + 255) / 256;

    detect_idx_kernel<<<1, 1>>>(ei);

    // ---- CSR build (graph shared by all layers) ----
    cudaMemsetAsync(cnt, 0, (size_t)N * sizeof(int));
    count_kernel<<<e_blocks, 256>>>(ei, E, cnt);
    scan_kernel<<<1, 1024>>>(cnt, rowptr, woff, N);
    fill_kernel<<<e_blocks, 256>>>(ei, E, woff, csr);

    // ---------------- Layer 1: H=4 (256 -> 256) ----------------
    run_gemm(x, W1, h, N, 256, 256);
    compute_al_kernel<4><<<al_blocks, 256>>>(h, as1, ad1, als, ald, N);
    run_gather<4, true>(rowptr, csr, h, als, ald, b1, buf, N);

    // ---------------- Layer 2: H=2 (256 -> 128) ----------------
    run_gemm(buf, W2, h, N, 256, 128);
    compute_al_kernel<2><<<al_blocks, 256>>>(h, as2, ad2, als, ald, N);
    run_gather<2, true>(rowptr, csr, h, als, ald, b2, buf, N);

    // ---------------- Layer 3: H=1 (128 -> 64) ----------------
    run_gemm(buf, W3, h, N, 128, 64);
    compute_al_kernel<1><<<al_blocks, 256>>>(h, as3, ad3, als, ald, N);
    run_gather<1, false>(rowptr, csr, h, als, ald, b3, buf, N);

    // ---------------- MHA (identity softmax) + heads ----------------
    prep_meff_kernel<<<1, 256>>>(Wqkv, bqkv, Wo, bo, meff, beff);
    heads_kernel<<<(N + 127) / 128, 128>>>(buf, meff, beff,
                                           Wlin, blin, Wcpu, bcpu, Wmem, bmem,
                                           (float*)d_out, N);
}

// round 5
// speedup vs baseline: 1.1226x; 1.0512x over previous
#include <cuda_runtime.h>

// ---------------------------------------------------------------------------
// Problem constants (shapes fixed by the dataset; N/E read at runtime)
// ---------------------------------------------------------------------------
#define NMAX 50000
#define EMAX 1000000

// Scratch (device globals; no allocation allowed)
__device__ float g_h  [NMAX * 256];   // GEMM output h of current layer
__device__ float g_buf[NMAX * 256];   // layer input / output buffer
__device__ float g_als[NMAX * 4];
__device__ float g_ald[NMAX * 4];
__device__ float g_meff[64 * 64];
__device__ float g_beff[64];
__device__ int   g_idx64;             // 1 if edge_index is int64, 0 if int32
__device__ int   g_cnt   [NMAX];
__device__ int   g_woff  [NMAX];
__device__ int   g_rowptr[NMAX + 1];
__device__ int   g_csr   [EMAX];

// ---------------------------------------------------------------------------
// Edge index dtype detection (int64 vs int32 stored in the same buffer).
// ---------------------------------------------------------------------------
__global__ void detect_idx_kernel(const void* ei)
{
    const long long* p = (const long long*)ei;
    int ok64 = 1;
#pragma unroll
    for (int i = 0; i < 8; i++) {
        long long v = p[i];
        if (v < 0 || v >= NMAX) ok64 = 0;
    }
    g_idx64 = ok64;
}

__device__ __forceinline__ int load_idx(const void* ei, long long i)
{
    if (g_idx64) return (int)((const long long*)ei)[i];
    return ((const int*)ei)[i];
}

// ---------------------------------------------------------------------------
// CSR build (graph is reused by all 3 layers). 4 edges per thread for MLP.
// ---------------------------------------------------------------------------
__global__ void count_kernel(const void* __restrict__ ei, int E, int* __restrict__ cnt)
{
    int e0 = (blockIdx.x * blockDim.x + threadIdx.x) * 4;
    int d[4];
#pragma unroll
    for (int i = 0; i < 4; i++)
        if (e0 + i < E) d[i] = load_idx(ei, (long long)E + e0 + i);
#pragma unroll
    for (int i = 0; i < 4; i++)
        if (e0 + i < E) atomicAdd(&cnt[d[i]], 1);
}

// Single-block exclusive scan over N counts -> rowptr (+ copy to woff).
__global__ __launch_bounds__(1024) void scan_kernel(
    const int* __restrict__ cnt, int* __restrict__ rowptr,
    int* __restrict__ woff, int N)
{
    __shared__ int ssum[1024];
    int t = threadIdx.x;
    int chunk = (N + 1023) / 1024;
    int s0 = t * chunk, s1 = min(s0 + chunk, N);
    if (s0 > N) s0 = N;

    int sum = 0;
    for (int i = s0; i < s1; i++) sum += cnt[i];
    ssum[t] = sum;
    __syncthreads();
    for (int o = 1; o < 1024; o <<= 1) {
        int v = (t >= o) ? ssum[t - o] : 0;
        __syncthreads();
        ssum[t] += v;
        __syncthreads();
    }
    int run = (t == 0) ? 0 : ssum[t - 1];
    for (int i = s0; i < s1; i++) {
        rowptr[i] = run;
        woff[i]   = run;
        run += cnt[i];
    }
    if (t == 1023) rowptr[N] = ssum[1023];
}

__global__ void fill_kernel(const void* __restrict__ ei, int E,
                            int* __restrict__ woff, int* __restrict__ csr_src)
{
    int e0 = (blockIdx.x * blockDim.x + threadIdx.x) * 4;
    int s[4], d[4];
#pragma unroll
    for (int i = 0; i < 4; i++)
        if (e0 + i < E) {
            s[i] = load_idx(ei, e0 + i);
            d[i] = load_idx(ei, (long long)E + e0 + i);
        }
#pragma unroll
    for (int i = 0; i < 4; i++)
        if (e0 + i < E) {
            int pos = atomicAdd(&woff[d[i]], 1);
            csr_src[pos] = s[i];
        }
}

// ---------------------------------------------------------------------------
// SGEMM: C[N,M] = A[N,K] @ B[K,M], row-major, fp32. Double-buffered smem.
// BM=128, BN=64, BK=16, 256 threads, 8x4 per thread.
// ---------------------------------------------------------------------------
#define BM 128
#define BN 64
#define BKK 16
#define TM 8
#define TN 4

__global__ __launch_bounds__(256) void sgemm_kernel(
    const float* __restrict__ A, const float* __restrict__ B,
    float* __restrict__ C, int Nrows, int K, int M)
{
    __shared__ float As[2][BKK][BM];
    __shared__ float Bs[2][BKK][BN];

    const int tid = threadIdx.x;
    const int block_row = blockIdx.y * BM;
    const int block_col = blockIdx.x * BN;

    const int aRow  = tid >> 2;        // 0..63
    const int aCol4 = tid & 3;
    const int bRow  = tid >> 4;        // 0..15
    const int bCol4 = tid & 15;

    const int ty = tid >> 4;
    const int tx = tid & 15;

    const int grow0 = block_row + aRow;
    const int grow1 = grow0 + 64;

    float acc[TM][TN];
#pragma unroll
    for (int i = 0; i < TM; i++)
#pragma unroll
        for (int j = 0; j < TN; j++) acc[i][j] = 0.f;

    float4 pa0, pa1, pb;
    // prologue: load tile 0
    pa0 = (grow0 < Nrows) ? *(const float4*)&A[(size_t)grow0 * K + aCol4 * 4]
                          : make_float4(0.f, 0.f, 0.f, 0.f);
    pa1 = (grow1 < Nrows) ? *(const float4*)&A[(size_t)grow1 * K + aCol4 * 4]
                          : make_float4(0.f, 0.f, 0.f, 0.f);
    pb  = *(const float4*)&B[(size_t)bRow * M + block_col + bCol4 * 4];

    int cur = 0;
    As[0][aCol4 * 4 + 0][aRow] = pa0.x;
    As[0][aCol4 * 4 + 1][aRow] = pa0.y;
    As[0][aCol4 * 4 + 2][aRow] = pa0.z;
    As[0][aCol4 * 4 + 3][aRow] = pa0.w;
    As[0][aCol4 * 4 + 0][aRow + 64] = pa1.x;
    As[0][aCol4 * 4 + 1][aRow + 64] = pa1.y;
    As[0][aCol4 * 4 + 2][aRow + 64] = pa1.z;
    As[0][aCol4 * 4 + 3][aRow + 64] = pa1.w;
    *(float4*)&Bs[0][bRow][bCol4 * 4] = pb;
    __syncthreads();

    for (int k0 = 0; k0 < K; k0 += BKK) {
        const bool hasNext = (k0 + BKK) < K;
        if (hasNext) {
            int kn = k0 + BKK;
            pa0 = (grow0 < Nrows) ? *(const float4*)&A[(size_t)grow0 * K + kn + aCol4 * 4]
                                  : make_float4(0.f, 0.f, 0.f, 0.f);
            pa1 = (grow1 < Nrows) ? *(const float4*)&A[(size_t)grow1 * K + kn + aCol4 * 4]
                                  : make_float4(0.f, 0.f, 0.f, 0.f);
            pb  = *(const float4*)&B[(size_t)(kn + bRow) * M + block_col + bCol4 * 4];
        }

#pragma unroll
        for (int k = 0; k < BKK; k++) {
            float ra[TM], rb[TN];
            float4 a0 = *(const float4*)&As[cur][k][ty * TM];
            float4 a1 = *(const float4*)&As[cur][k][ty * TM + 4];
            ra[0]=a0.x; ra[1]=a0.y; ra[2]=a0.z; ra[3]=a0.w;
            ra[4]=a1.x; ra[5]=a1.y; ra[6]=a1.z; ra[7]=a1.w;
            float4 b0 = *(const float4*)&Bs[cur][k][tx * TN];
            rb[0]=b0.x; rb[1]=b0.y; rb[2]=b0.z; rb[3]=b0.w;
#pragma unroll
            for (int i = 0; i < TM; i++)
#pragma unroll
                for (int j = 0; j < TN; j++)
                    acc[i][j] = fmaf(ra[i], rb[j], acc[i][j]);
        }

        if (hasNext) {
            int nxt = cur ^ 1;
            As[nxt][aCol4 * 4 + 0][aRow] = pa0.x;
            As[nxt][aCol4 * 4 + 1][aRow] = pa0.y;
            As[nxt][aCol4 * 4 + 2][aRow] = pa0.z;
            As[nxt][aCol4 * 4 + 3][aRow] = pa0.w;
            As[nxt][aCol4 * 4 + 0][aRow + 64] = pa1.x;
            As[nxt][aCol4 * 4 + 1][aRow + 64] = pa1.y;
            As[nxt][aCol4 * 4 + 2][aRow + 64] = pa1.z;
            As[nxt][aCol4 * 4 + 3][aRow + 64] = pa1.w;
            *(float4*)&Bs[nxt][bRow][bCol4 * 4] = pb;
            __syncthreads();
            cur = nxt;
        }
    }

#pragma unroll
    for (int i = 0; i < TM; i++) {
        int grow = block_row + ty * TM + i;
        if (grow < Nrows) {
            float4 v = make_float4(acc[i][0], acc[i][1], acc[i][2], acc[i][3]);
            *(float4*)&C[(size_t)grow * M + block_col + tx * TN] = v;
        }
    }
}

// ---------------------------------------------------------------------------
// Per-node attention logits
// ---------------------------------------------------------------------------
template <int H>
__global__ void compute_al_kernel(const float* __restrict__ h,
                                  const float* __restrict__ a_src,
                                  const float* __restrict__ a_dst,
                                  float* __restrict__ als,
                                  float* __restrict__ ald, int N)
{
    int n    = (blockIdx.x * blockDim.x + threadIdx.x) >> 5;
    int lane = threadIdx.x & 31;
    if (n >= N) return;
    const float* hn = h + (size_t)n * (H * 64);
#pragma unroll
    for (int hd = 0; hd < H; hd++) {
        float v1 = hn[hd * 64 + lane];
        float v2 = hn[hd * 64 + 32 + lane];
        float s  = v1 * a_src[hd * 64 + lane] + v2 * a_src[hd * 64 + 32 + lane];
        float d  = v1 * a_dst[hd * 64 + lane] + v2 * a_dst[hd * 64 + 32 + lane];
#pragma unroll
        for (int o = 16; o > 0; o >>= 1) {
            s += __shfl_down_sync(0xffffffffu, s, o);
            d += __shfl_down_sync(0xffffffffu, d, o);
        }
        if (lane == 0) {
            als[n * H + hd] = s;
            ald[n * H + hd] = d;
        }
    }
}

// ---------------------------------------------------------------------------
// Fused CSR gather, 4-edge batched for MLP. One node per LPE-lane group.
// ---------------------------------------------------------------------------
template <int H, bool DOELU>
__global__ __launch_bounds__(256) void gat_gather_kernel(
    const int* __restrict__ rowptr, const int* __restrict__ csr_src,
    const float* __restrict__ h, const float* __restrict__ als,
    const float* __restrict__ ald, const float* __restrict__ bias,
    float* __restrict__ out, int N)
{
    constexpr int F4  = H * 16;                 // float4 per node row
    constexpr int LPE = (F4 < 32) ? F4 : 32;    // lanes per node
    constexpr int NPW = 32 / LPE;               // nodes per warp
    constexpr int F4L = (F4 + 31) / 32;         // float4 per lane

    int gwarp = (blockIdx.x * blockDim.x + threadIdx.x) >> 5;
    int lane  = threadIdx.x & 31;
    int sub   = lane % LPE;
    int base  = lane - sub;
    const unsigned mask = (LPE == 32) ? 0xffffffffu
                                      : (((1u << LPE) - 1u) << base);
    int n     = gwarp * NPW + lane / LPE;
    bool valid = (n < N);
    if (!valid) n = 0;

    int rb = rowptr[n], re = rowptr[n + 1];
    if (!valid) { rb = 0; re = 0; }

    float aldh = 0.f, alsh = 0.f;
    if (sub < H) {
        aldh = ald[(size_t)n * H + sub];
        alsh = als[(size_t)n * H + sub];
    }

    float4 acc[F4L];
#pragma unroll
    for (int t = 0; t < F4L; t++) acc[t] = make_float4(0.f, 0.f, 0.f, 0.f);
    float den = 0.f;

    // self loop
    {
        float exs = 0.f;
        if (sub < H) {
            float s = alsh + aldh;
            s = s > 0.f ? s : 0.2f * s;
            exs = __expf(s);
            den = exs;
        }
#pragma unroll
        for (int t = 0; t < F4L; t++) {
            int q = sub + t * LPE;
            float ex = __shfl_sync(mask, exs, base + (q >> 4));
            float4 hv = *(const float4*)(h + (size_t)n * (F4 * 4) + q * 4);
            acc[t].x += hv.x * ex; acc[t].y += hv.y * ex;
            acc[t].z += hv.z * ex; acc[t].w += hv.w * ex;
        }
    }

    // neighbors, 4 at a time
    for (int e = rb; e < re; e += 4) {
        int m = re - e; if (m > 4) m = 4;

        int srcs[4];
#pragma unroll
        for (int i = 0; i < 4; i++)
            if (i < m) srcs[i] = csr_src[e + i];

        float alv[4];
#pragma unroll
        for (int i = 0; i < 4; i++)
            if (i < m && sub < H) alv[i] = als[(size_t)srcs[i] * H + sub];

        float4 hv[4][F4L];
#pragma unroll
        for (int i = 0; i < 4; i++)
            if (i < m)
#pragma unroll
                for (int t = 0; t < F4L; t++) {
                    int q = sub + t * LPE;
                    hv[i][t] = *(const float4*)(h + (size_t)srcs[i] * (F4 * 4) + q * 4);
                }

        float exv[4];
#pragma unroll
        for (int i = 0; i < 4; i++) {
            exv[i] = 0.f;
            if (i < m && sub < H) {
                float s = alv[i] + aldh;
                s = s > 0.f ? s : 0.2f * s;
                exv[i] = __expf(s);
                den += exv[i];
            }
        }

#pragma unroll
        for (int i = 0; i < 4; i++)
            if (i < m)
#pragma unroll
                for (int t = 0; t < F4L; t++) {
                    int q = sub + t * LPE;
                    float ex = __shfl_sync(mask, exv[i], base + (q >> 4));
                    acc[t].x += hv[i][t].x * ex; acc[t].y += hv[i][t].y * ex;
                    acc[t].z += hv[i][t].z * ex; acc[t].w += hv[i][t].w * ex;
                }
    }

    // normalize + bias (+ ELU) + store
    float inv = 0.f;
    if (sub < H) inv = 1.f / (den + 1e-16f);
#pragma unroll
    for (int t = 0; t < F4L; t++) {
        int q = sub + t * LPE;
        float iv = __shfl_sync(mask, inv, base + (q >> 4));
        float4 bv = *(const float4*)(bias + q * 4);
        float4 o;
        o.x = acc[t].x * iv + bv.x;
        o.y = acc[t].y * iv + bv.y;
        o.z = acc[t].z * iv + bv.z;
        o.w = acc[t].w * iv + bv.w;
        if (DOELU) {
            o.x = o.x > 0.f ? o.x : (__expf(o.x) - 1.f);
            o.y = o.y > 0.f ? o.y : (__expf(o.y) - 1.f);
            o.z = o.z > 0.f ? o.z : (__expf(o.z) - 1.f);
            o.w = o.w > 0.f ? o.w : (__expf(o.w) - 1.f);
        }
        if (valid)
            *(float4*)(out + (size_t)n * (F4 * 4) + q * 4) = o;
    }
}

// ---------------------------------------------------------------------------
// Fold MHA (seq_len=1 => softmax == 1 => a = h @ (Wo @ Wqkv_v)^T + fold bias)
// ---------------------------------------------------------------------------
__global__ void prep_meff_kernel(const float* __restrict__ Wqkv,
                                 const float* __restrict__ bqkv,
                                 const float* __restrict__ Wo,
                                 const float* __restrict__ bo,
                                 float* __restrict__ Meff,
                                 float* __restrict__ beff)
{
    int idx = threadIdx.x;
    for (int t = idx; t < 4096; t += blockDim.x) {
        int i = t >> 6, j = t & 63;
        float s = 0.f;
#pragma unroll
        for (int k = 0; k < 64; k++)
            s += Wo[i * 64 + k] * Wqkv[(128 + k) * 64 + j];
        Meff[t] = s;
    }
    if (idx < 64) {
        float s = bo[idx];
#pragma unroll
        for (int k = 0; k < 64; k++)
            s += Wo[idx * 64 + k] * bqkv[128 + k];
        beff[idx] = s;
    }
}

// ---------------------------------------------------------------------------
// Final heads
// ---------------------------------------------------------------------------
__global__ __launch_bounds__(128) void heads_kernel(
    const float* __restrict__ h3,
    const float* __restrict__ Meff, const float* __restrict__ beff,
    const float* __restrict__ Wlin, const float* __restrict__ blin,
    const float* __restrict__ Wcpu, const float* __restrict__ bcpu,
    const float* __restrict__ Wmem, const float* __restrict__ bmem,
    float* __restrict__ out, int N)
{
    __shared__ float sM[64 * 64];
    __shared__ float sbeff[64];
    __shared__ float sW[5 * 64];
    __shared__ float sbb[5];

    int tid = threadIdx.x;
    for (int t = tid; t < 4096; t += blockDim.x) sM[t] = Meff[t];
    if (tid < 64) sbeff[tid] = beff[tid];
    for (int t = tid; t < 192; t += blockDim.x) sW[t] = Wlin[t];
    if (tid < 64) sW[192 + tid] = Wcpu[tid];
    if (tid < 64) sW[256 + tid] = Wmem[tid];
    if (tid == 0) { sbb[0]=blin[0]; sbb[1]=blin[1]; sbb[2]=blin[2]; sbb[3]=bcpu[0]; sbb[4]=bmem[0]; }
    __syncthreads();

    int n = blockIdx.x * blockDim.x + tid;
    if (n >= N) return;

    float hreg[64];
    const float4* hp = (const float4*)(h3 + (size_t)n * 64);
#pragma unroll
    for (int i = 0; i < 16; i++) {
        float4 v = hp[i];
        hreg[i*4+0]=v.x; hreg[i*4+1]=v.y; hreg[i*4+2]=v.z; hreg[i*4+3]=v.w;
    }

    float o0 = sbb[0], o1 = sbb[1], o2 = sbb[2], o3 = sbb[3], o4 = sbb[4];
    for (int i = 0; i < 64; i++) {
        float a = sbeff[i];
        const float* mi = &sM[i * 64];
#pragma unroll
        for (int j = 0; j < 64; j++) a = fmaf(hreg[j], mi[j], a);
        o0 = fmaf(sW[0 * 64 + i], a, o0);
        o1 = fmaf(sW[1 * 64 + i], a, o1);
        o2 = fmaf(sW[2 * 64 + i], a, o2);
        o3 = fmaf(sW[3 * 64 + i], a, o3);
        o4 = fmaf(sW[4 * 64 + i], a, o4);
    }
    out[n * 3 + 0] = o0;
    out[n * 3 + 1] = o1;
    out[n * 3 + 2] = o2;
    out[3 * N + n] = 1.f / (1.f + __expf(-o3));
    out[4 * N + n] = 1.f / (1.f + __expf(-o4));
}

// ---------------------------------------------------------------------------
// Host-side orchestration
// ---------------------------------------------------------------------------
static inline void run_gemm(const float* A, const float* B, float* C,
                            int Nrows, int K, int M)
{
    dim3 grid(M / BN, (Nrows + BM - 1) / BM);
    sgemm_kernel<<<grid, 256>>>(A, B, C, Nrows, K, M);
}

template <int H, bool DOELU>
static inline void run_gather(const int* rowptr, const int* csr,
                              const float* h, const float* als,
                              const float* ald, const float* bias,
                              float* out, int N)
{
    constexpr int F4  = H * 16;
    constexpr int LPE = (F4 < 32) ? F4 : 32;
    constexpr int NPW = 32 / LPE;
    int warps  = (N + NPW - 1) / NPW;
    int blocks = (warps * 32 + 255) / 256;
    gat_gather_kernel<H, DOELU><<<blocks, 256>>>(rowptr, csr, h, als, ald, bias, out, N);
}

extern "C" void kernel_launch(void* const* d_in, const int* in_sizes, int n_in,
                              void* d_out, int out_size)
{
    const float* x    = (const float*)d_in[0];
    const void*  ei   = d_in[1];
    const float* W1   = (const float*)d_in[2];
    const float* as1  = (const float*)d_in[3];
    const float* ad1  = (const float*)d_in[4];
    const float* b1   = (const float*)d_in[5];
    const float* W2   = (const float*)d_in[6];
    const float* as2  = (const float*)d_in[7];
    const float* ad2  = (const float*)d_in[8];
    const float* b2   = (const float*)d_in[9];
    const float* W3   = (const float*)d_in[10];
    const float* as3  = (const float*)d_in[11];
    const float* ad3  = (const float*)d_in[12];
    const float* b3   = (const float*)d_in[13];
    const float* Wqkv = (const float*)d_in[14];
    const float* bqkv = (const float*)d_in[15];
    const float* Wo   = (const float*)d_in[16];
    const float* bo   = (const float*)d_in[17];
    const float* Wlin = (const float*)d_in[18];
    const float* blin = (const float*)d_in[19];
    const float* Wcpu = (const float*)d_in[20];
    const float* bcpu = (const float*)d_in[21];
    const float* Wmem = (const float*)d_in[22];
    const float* bmem = (const float*)d_in[23];

    const int N = in_sizes[0] / 256;
    const int E = in_sizes[1] / 2;

    float *h, *buf, *als, *ald, *meff, *beff;
    int *cnt, *woff, *rowptr, *csr;
    cudaGetSymbolAddress((void**)&h,      g_h);
    cudaGetSymbolAddress((void**)&buf,    g_buf);
    cudaGetSymbolAddress((void**)&als,    g_als);
    cudaGetSymbolAddress((void**)&ald,    g_ald);
    cudaGetSymbolAddress((void**)&meff,   g_meff);
    cudaGetSymbolAddress((void**)&beff,   g_beff);
    cudaGetSymbolAddress((void**)&cnt,    g_cnt);
    cudaGetSymbolAddress((void**)&woff,   g_woff);
    cudaGetSymbolAddress((void**)&rowptr, g_rowptr);
    cudaGetSymbolAddress((void**)&csr,    g_csr);

    const int al_blocks = (N * 32 + 255) / 256;
    const int e_blocks4 = (E + 1023) / 1024;

    detect_idx_kernel<<<1, 1>>>(ei);

    // ---- CSR build (graph shared by all layers) ----
    cudaMemsetAsync(cnt, 0, (size_t)N * sizeof(int));
    count_kernel<<<e_blocks4, 256>>>(ei, E, cnt);
    scan_kernel<<<1, 1024>>>(cnt, rowptr, woff, N);
    fill_kernel<<<e_blocks4, 256>>>(ei, E, woff, csr);

    // ---------------- Layer 1: H=4 (256 -> 256) ----------------
    run_gemm(x, W1, h, N, 256, 256);
    compute_al_kernel<4><<<al_blocks, 256>>>(h, as1, ad1, als, ald, N);
    run_gather<4, true>(rowptr, csr, h, als, ald, b1, buf, N);

    // ---------------- Layer 2: H=2 (256 -> 128) ----------------
    run_gemm(buf, W2, h, N, 256, 128);
    compute_al_kernel<2><<<al_blocks, 256>>>(h, as2, ad2, als, ald, N);
    run_gather<2, true>(rowptr, csr, h, als, ald, b2, buf, N);

    // ---------------- Layer 3: H=1 (128 -> 64) ----------------
    run_gemm(buf, W3, h, N, 128, 64);
    compute_al_kernel<1><<<al_blocks, 256>>>(h, as3, ad3, als, ald, N);
    run_gather<1, false>(rowptr, csr, h, als, ald, b3, buf, N);

    // ---------------- MHA (identity softmax) + heads ----------------
    prep_meff_kernel<<<1, 256>>>(Wqkv, bqkv, Wo, bo, meff, beff);
    heads_kernel<<<(N + 127) / 128, 128>>>(buf, meff, beff,
                                           Wlin, blin, Wcpu, bcpu, Wmem, bmem,
                                           (float*)d_out, N);
}